// round 8
// baseline (speedup 1.0000x reference)
#include <cuda_runtime.h>
#include <math.h>

#define NLAT 361
#define NLON 720
#define NBC  16        // 2 batches * 8 channels
#define NCH  32        // 2 tensors * 16 complex channels
#define KDEG 360
#define EPSV 1e-7f
#define R_TOT  11552
#define R_PAD  11584   // 362 * 32
#define HALF_R 5776
#define NPAD   384     // padded folded-n dimension (n = 0..360 real)
#define MP2    96      // padded m-pair count (mp 0..90 real -> m 0..181)
#define PI_F 3.14159265358979323846f

typedef unsigned long long ull;

// ---------------- scratch ----------------------------------------------------
__device__ float  g_S[(size_t)R_PAD * NPAD];              // folded sums
__device__ float  g_D[(size_t)R_PAD * NPAD];              // folded diffs
__device__ float2 g_Bc[NPAD * MP2];                       // {cos(m0),cos(m1)}
__device__ float2 g_Bs[NPAD * MP2];                       // {-sin(m0),-sin(m1)}
__device__ float2 g_F[(size_t)NLAT * NCH * NLAT];         // [m][c32][j]
__device__ float  g_stats[KDEG * NBC * 4];                // [l][bc]{pp,tp,sr,si}

// ---------------- helpers ----------------------------------------------------
__device__ __forceinline__ ull pk2(float x, float y) {
    ull r; asm("mov.b64 %0, {%1, %2};" : "=l"(r) : "f"(x), "f"(y)); return r;
}
__device__ __forceinline__ float2 upk2(ull v) {
    float2 r; asm("mov.b64 {%0, %1}, %2;" : "=f"(r.x), "=f"(r.y) : "l"(v)); return r;
}
__device__ __forceinline__ void fma2(ull &d, ull a, ull b) {
    asm("fma.rn.f32x2 %0, %1, %2, %0;" : "+l"(d) : "l"(a), "l"(b));
}
__device__ __forceinline__ unsigned su32(const void* p) {
    return (unsigned)__cvta_generic_to_shared(p);
}
#define CP_ASYNC_8(dst, src) \
    asm volatile("cp.async.ca.shared.global [%0], [%1], 8;" :: "r"(dst), "l"(src))
#define CP_ASYNC_4(dst, src) \
    asm volatile("cp.async.ca.shared.global [%0], [%1], 4;" :: "r"(dst), "l"(src))
#define CP_COMMIT  asm volatile("cp.async.commit_group;")
#define CP_WAIT1   asm volatile("cp.async.wait_group 1;")
#define CP_WAIT0   asm volatile("cp.async.wait_group 0;")

// ---------------- K0a: twiddle tables (m 0..181) + zero stats ---------------
__global__ void k0_tables() {
    int tid = blockIdx.x * blockDim.x + threadIdx.x;
    int stride = gridDim.x * blockDim.x;
    const int NT = NPAD * MP2;
    for (int i = tid; i < NT; i += stride) {
        int n = i / MP2, mp = i - (i / MP2) * MP2;
        float c0 = 0.f, s0 = 0.f, c1 = 0.f, s1 = 0.f;
        if (n <= 360) {
            int m0 = 2 * mp, m1 = m0 + 1;
            if (m0 <= 181) {
                float s, c;
                sincospif((float)((n * m0) % NLON) / 360.f, &s, &c);
                c0 = c; s0 = -s;
            }
            if (m1 <= 181) {
                float s, c;
                sincospif((float)((n * m1) % NLON) / 360.f, &s, &c);
                c1 = c; s1 = -s;
            }
        }
        g_Bc[i] = make_float2(c0, c1);
        g_Bs[i] = make_float2(s0, s1);
    }
    for (int i = tid; i < KDEG * NBC * 4; i += stride) g_stats[i] = 0.f;
}

// ---------------- K0b: fold rows into sum/diff with quadrature scale --------
__global__ void k0b_sd(const float* __restrict__ pred,
                       const float* __restrict__ targ,
                       const float* __restrict__ w) {
    const int NQ = NPAD / 4;  // 96 float4 per row
    int id = blockIdx.x * blockDim.x + threadIdx.x;
    if (id >= R_PAD * NQ) return;
    int r = id / NQ;
    int n = (id - r * NQ) * 4;
    float4 sv = make_float4(0.f, 0.f, 0.f, 0.f);
    float4 dv = make_float4(0.f, 0.f, 0.f, 0.f);
    if (r < R_TOT) {
        int tensor = r / HALF_R;
        int rem = r - tensor * HALF_R;
        int j = rem % NLAT;
        float wsc = w[j] * (2.f * PI_F / (float)NLON);
        const float* a = (tensor ? targ : pred) + (size_t)rem * NLON;
        float4 af = *(const float4*)(a + n);
        float fa[4] = {af.x, af.y, af.z, af.w};
        float so[4], dd[4];
#pragma unroll
        for (int e = 0; e < 4; e++) {
            int nn = n + e;
            float av = (nn <= 360) ? fa[e] : 0.f;
            float mv = (nn >= 1 && nn <= 359) ? a[NLON - nn] : 0.f;
            so[e] = (av + mv) * wsc;
            dd[e] = (av - mv) * wsc;
        }
        sv = make_float4(so[0], so[1], so[2], so[3]);
        dv = make_float4(dd[0], dd[1], dd[2], dd[3]);
    }
    *(float4*)&g_S[(size_t)r * NPAD + n] = sv;
    *(float4*)&g_D[(size_t)r * NPAD + n] = dv;
}

// ---------------- K1: folded DFT with m <-> 360-m mirror fold ---------------
__global__ __launch_bounds__(128, 4) void k1_dft() {
    __shared__ float2 Ss[32][16];     // [row][q] = {s[2q], s[2q+1]}
    __shared__ float2 Ds[32][16];
    __shared__ float2 Cs[32][32];     // [n_local][mp]
    __shared__ float2 Sn[32][32];

    const int t    = threadIdx.x;
    const int mp0  = blockIdx.x * 32;
    const int row0 = blockIdx.y * 32;
    const int tcol = t & 15;
    const int trow = t >> 4;
    const int tc2  = tcol * 2;

    ull aCe[4][2], aCo[4][2], aSe[4][2], aSo[4][2];
    const ull z = pk2(0.f, 0.f);
#pragma unroll
    for (int i = 0; i < 4; i++)
#pragma unroll
        for (int p = 0; p < 2; p++) {
            aCe[i][p] = z; aCo[i][p] = z; aSe[i][p] = z; aSo[i][p] = z;
        }

    for (int kt = 0; kt < 12; kt++) {
        const int k0 = kt * 32;
#pragma unroll
        for (int q = 0; q < 2; q++) {
            int f = t + q * 128;
            int row = f >> 3, c4 = f & 7;
            size_t gi = (size_t)(row0 + row) * NPAD + k0 + c4 * 4;
            float4 v = *(const float4*)&g_S[gi];
            Ss[row][c4 * 2]     = make_float2(v.x, v.y);
            Ss[row][c4 * 2 + 1] = make_float2(v.z, v.w);
            float4 u = *(const float4*)&g_D[gi];
            Ds[row][c4 * 2]     = make_float2(u.x, u.y);
            Ds[row][c4 * 2 + 1] = make_float2(u.z, u.w);
        }
#pragma unroll
        for (int q = 0; q < 4; q++) {
            int e = t + q * 128;
            int nl = e >> 4, f4 = e & 15;
            size_t gi = (size_t)(k0 + nl) * MP2 + mp0;
            ((float4*)&Cs[nl][0])[f4] = ((const float4*)&g_Bc[gi])[f4];
            ((float4*)&Sn[nl][0])[f4] = ((const float4*)&g_Bs[gi])[f4];
        }
        __syncthreads();
#pragma unroll 4
        for (int q = 0; q < 16; q++) {
            ulonglong2 ce = *(const ulonglong2*)&Cs[2 * q][tc2];
            ulonglong2 co = *(const ulonglong2*)&Cs[2 * q + 1][tc2];
            ulonglong2 se = *(const ulonglong2*)&Sn[2 * q][tc2];
            ulonglong2 so = *(const ulonglong2*)&Sn[2 * q + 1][tc2];
#pragma unroll
            for (int i = 0; i < 4; i++) {
                float2 sv = Ss[trow * 4 + i][q];
                float2 dv = Ds[trow * 4 + i][q];
                ull sae = pk2(sv.x, sv.x), sao = pk2(sv.y, sv.y);
                ull dae = pk2(dv.x, dv.x), dao = pk2(dv.y, dv.y);
                fma2(aCe[i][0], sae, ce.x); fma2(aCe[i][1], sae, ce.y);
                fma2(aCo[i][0], sao, co.x); fma2(aCo[i][1], sao, co.y);
                fma2(aSe[i][0], dae, se.x); fma2(aSe[i][1], dae, se.y);
                fma2(aSo[i][0], dao, so.x); fma2(aSo[i][1], dao, so.y);
            }
        }
        __syncthreads();
    }

#pragma unroll
    for (int i = 0; i < 4; i++) {
        int gr = row0 + trow * 4 + i;
        if (gr >= R_TOT) continue;
        int tensor = gr / HALF_R;
        int rem = gr - tensor * HALF_R;
        int bc = rem / NLAT;
        int j  = rem - bc * NLAT;
        int c  = tensor * 16 + bc;
        float2* Fc = &g_F[(size_t)c * NLAT + j];
#pragma unroll
        for (int p = 0; p < 2; p++) {
            int g  = mp0 + tc2 + p;
            int m0 = 2 * g, m1 = m0 + 1;
            float2 ce = upk2(aCe[i][p]), co = upk2(aCo[i][p]);
            float2 se = upk2(aSe[i][p]), so = upk2(aSo[i][p]);
            if (m0 <= 180)
                Fc[(size_t)m0 * (NCH * NLAT)] = make_float2(ce.x + co.x, se.x + so.x);
            if (m1 <= 180)
                Fc[(size_t)m1 * (NCH * NLAT)] = make_float2(ce.y + co.y, se.y + so.y);
            if (m0 <= 179)
                Fc[(size_t)(360 - m0) * (NCH * NLAT)] =
                    make_float2(ce.x - co.x, -se.x + so.x);
            if (m1 <= 179)
                Fc[(size_t)(360 - m1) * (NCH * NLAT)] =
                    make_float2(ce.y - co.y, -se.y + so.y);
        }
    }
}

// ---------------- K2: Legendre contraction, cp.async double-buffered --------
#define TJ 16
#define NTILE 12
__global__ __launch_bounds__(128, 4) void k2_leg(const float* __restrict__ leg) {
    const int m  = blockIdx.y;                 // 0..359
    const int l0 = m + blockIdx.x * 128;
    if (l0 >= KDEG) return;

    __shared__ float2 Fa[2][32][18];           // raw F(j),   [buf][c][u]
    __shared__ float2 Fb[2][32][18];           // raw F(360-j) reversed
    __shared__ float  Ls[2][128][17];          // leg, [buf][l][jl]
    __shared__ float2 Fse[TJ][34];             // folded even  [jl][c]
    __shared__ float2 Fso[TJ][34];             // folded odd

    const int t   = threadIdx.x;
    const int cg  = t & 7;
    const int lg  = t >> 3;
    const int ch0 = cg * 4;
    const int lb  = lg * 8;

    // staging maps
    const int cA   = t >> 2;                   // 0..31 channel for F staging
    const int ub   = (t & 3) * 4;              // u-chunk base
    const int lcl  = min(l0 + t, 360);         // clamped leg row (garbage rows discarded)
    const float2* Fm   = &g_F[(size_t)m * NCH * NLAT];
    const float2* srcA = Fm + (size_t)cA * NLAT;        // + j0 + u
    const float2* srcB = Fm + (size_t)cA * NLAT + 345;  // - j0 + u
    const float*  srcL = leg + ((size_t)lcl * NLAT + m) * NLAT;  // + j0 + jl

    ull acc[8][4];
    const ull z = pk2(0.f, 0.f);
#pragma unroll
    for (int i = 0; i < 8; i++)
#pragma unroll
        for (int k = 0; k < 4; k++) acc[i][k] = z;

    // async stage of one full tile (tiles 0..10 only)
    auto stage_async = [&](int tile, int b) {
        const int j0 = tile * TJ;
#pragma unroll
        for (int e = 0; e < 4; e++) {
            int u = ub + e;
            CP_ASYNC_8(su32(&Fa[b][cA][u]), srcA + j0 + u);
            CP_ASYNC_8(su32(&Fb[b][cA][u]), srcB - j0 + u);
        }
#pragma unroll
        for (int q = 0; q < 16; q++)
            CP_ASYNC_4(su32(&Ls[b][t][q]), srcL + j0 + q);
    };

    stage_async(0, 0);
    CP_COMMIT;

    for (int tile = 0; tile < NTILE; tile++) {
        const int buf = tile & 1;
        if (tile < 10)      { stage_async(tile + 1, buf ^ 1); CP_COMMIT; CP_WAIT1; }
        else if (tile == 10){ CP_WAIT0; }
        __syncthreads();

        if (tile == 11) {
            // synchronous slow path: j0 = 176, midpoint j=180, padding beyond
            const int j0 = 176;
#pragma unroll
            for (int e = 0; e < 4; e++) {
                int u = ub + e;
                int ja = j0 + u;               // j for Fa slot u
                Fa[buf][cA][u] = (ja <= 180) ? srcA[ja] : make_float2(0.f, 0.f);
                // Fb slot u is read at jl = 15-u  ->  j = 191-u ; mirror valid iff j<180
                Fb[buf][cA][u] = (u >= 12) ? srcA[169 + u] : make_float2(0.f, 0.f);
            }
#pragma unroll
            for (int q = 0; q < 16; q++) {
                int j = j0 + q;
                Ls[buf][t][q] = (j <= 180 && (l0 + t) <= 360) ? srcL[j] : 0.f;
            }
            __syncthreads();
        }

        // fold pass: Fse/Fso[jl][c] from raw Fa/Fb
        {
            const int jl = t & 15, c0 = t >> 4;
#pragma unroll
            for (int q = 0; q < 4; q++) {
                int c = c0 + 8 * q;
                float2 a  = Fa[buf][c][jl];
                float2 bb = Fb[buf][c][15 - jl];
                Fse[jl][c] = make_float2(a.x + bb.x, a.y + bb.y);
                Fso[jl][c] = make_float2(a.x - bb.x, a.y - bb.y);
            }
        }
        __syncthreads();

        // compute
#pragma unroll 4
        for (int jl = 0; jl < TJ; jl++) {
            ulonglong2 fe01 = *(const ulonglong2*)&Fse[jl][ch0];
            ulonglong2 fe23 = *(const ulonglong2*)&Fse[jl][ch0 + 2];
            ulonglong2 fo01 = *(const ulonglong2*)&Fso[jl][ch0];
            ulonglong2 fo23 = *(const ulonglong2*)&Fso[jl][ch0 + 2];
#pragma unroll
            for (int i = 0; i < 8; i++) {
                float lv = Ls[buf][lb + i][jl];
                ull l2 = pk2(lv, lv);
                if (i & 1) {
                    fma2(acc[i][0], l2, fo01.x); fma2(acc[i][1], l2, fo01.y);
                    fma2(acc[i][2], l2, fo23.x); fma2(acc[i][3], l2, fo23.y);
                } else {
                    fma2(acc[i][0], l2, fe01.x); fma2(acc[i][1], l2, fe01.y);
                    fma2(acc[i][2], l2, fe23.x); fma2(acc[i][3], l2, fe23.y);
                }
            }
        }
        __syncthreads();
    }

    // epilogue: pair P (cg<4) with T (cg+4) via shfl, atomically accumulate
    const float wm = (m == 0) ? 1.f : 2.f;
#pragma unroll
    for (int i = 0; i < 8; i++) {
        int l = l0 + lb + i;
#pragma unroll
        for (int k = 0; k < 4; k++) {
            float2 cv = upk2(acc[i][k]);
            float ox = __shfl_xor_sync(0xffffffffu, cv.x, 4);
            float oy = __shfl_xor_sync(0xffffffffu, cv.y, 4);
            if (cg < 4 && l < KDEG) {
                float pp  = cv.x * cv.x + cv.y * cv.y;
                float tp  = ox * ox + oy * oy;
                float crr = cv.x * ox + cv.y * oy;
                float cii = cv.x * oy - cv.y * ox;
                float* s = &g_stats[(l * NBC + ch0 + k) * 4];
                atomicAdd(s + 0, wm * pp);
                atomicAdd(s + 1, wm * tp);
                atomicAdd(s + 2, wm * crr);
                atomicAdd(s + 3, wm * cii);
            }
        }
    }
}

// ---------------- K3: final loss --------------------------------------------
__global__ void k3_final(const float* __restrict__ weights, float* __restrict__ out) {
    __shared__ float red[32];
    const int t = threadIdx.x;                 // 1024 threads
    float part = 0.f;
    for (int i = t; i < KDEG * NBC; i += 1024) {
        float4 s = *(const float4*)&g_stats[i * 4];
        int bc = i & 15;
        float pp = s.x + EPSV;
        float tp = s.y + EPSV;
        float mag = sqrtf(s.z * s.z + s.w * s.w);
        float den = sqrtf(pp * tp + EPSV) + EPSV;
        float coh = fminf(mag / den, 1.f);
        float sp = sqrtf(pp), st = sqrtf(tp);
        float amp = (sp - st) * (sp - st);
        float dec = 2.f * fmaxf(pp, tp) * (1.f - coh);
        part += weights[bc & 7] * (amp + dec);
    }
#pragma unroll
    for (int o = 16; o > 0; o >>= 1) part += __shfl_down_sync(0xffffffffu, part, o);
    if ((t & 31) == 0) red[t >> 5] = part;
    __syncthreads();
    if (t < 32) {
        float v = red[t];
#pragma unroll
        for (int o = 16; o > 0; o >>= 1) v += __shfl_down_sync(0xffffffffu, v, o);
        if (t == 0) {
            float loss = v / (float)(KDEG * NBC);
            if (isnan(loss)) loss = 1e6f;
            out[0] = loss;
        }
    }
}

// ---------------- launcher ---------------------------------------------------
extern "C" void kernel_launch(void* const* d_in, const int* in_sizes, int n_in,
                              void* d_out, int out_size) {
    const float* pred    = (const float*)d_in[0];
    const float* targ    = (const float*)d_in[1];
    const float* weights = (const float*)d_in[2];
    const float* leg     = (const float*)d_in[3];
    const float* w       = (const float*)d_in[4];

    k0_tables<<<144, 256>>>();

    int tot0 = R_PAD * (NPAD / 4);
    k0b_sd<<<(tot0 + 255) / 256, 256>>>(pred, targ, w);

    dim3 g1(3, 362);            // 32 mp-tiles x 32-row tiles
    k1_dft<<<g1, 128>>>();

    dim3 g2(3, KDEG);           // 128-l tiles x m
    k2_leg<<<g2, 128>>>(leg);

    k3_final<<<1, 1024>>>(weights, (float*)d_out);
}

// round 9
// speedup vs baseline: 1.0218x; 1.0218x over previous
#include <cuda_runtime.h>
#include <math.h>

#define NLAT 361
#define NLON 720
#define NBC  16        // 2 batches * 8 channels
#define NCH  32        // 2 tensors * 16 complex channels
#define KDEG 360
#define EPSV 1e-7f
#define R_TOT  11552
#define R_PAD  11584   // 362 * 32
#define HALF_R 5776
#define NPAD   384     // padded folded-n dimension (n = 0..360 real)
#define MP2    96      // padded m-pair count (mp 0..90 real -> m 0..181)
#define PI_F 3.14159265358979323846f

typedef unsigned long long ull;

// ---------------- scratch ----------------------------------------------------
__device__ float  g_S[(size_t)R_PAD * NPAD];              // folded sums
__device__ float  g_D[(size_t)R_PAD * NPAD];              // folded diffs
__device__ float2 g_Bc[NPAD * MP2];                       // {cos(m0),cos(m1)}
__device__ float2 g_Bs[NPAD * MP2];                       // {-sin(m0),-sin(m1)}
__device__ float2 g_F[(size_t)NLAT * NCH * NLAT];         // [m][c32][j]
__device__ float  g_stats[KDEG * NBC * 4];                // [l][bc]{pp,tp,sr,si}

// ---------------- f32x2 helpers ---------------------------------------------
__device__ __forceinline__ ull pk2(float x, float y) {
    ull r; asm("mov.b64 %0, {%1, %2};" : "=l"(r) : "f"(x), "f"(y)); return r;
}
__device__ __forceinline__ float2 upk2(ull v) {
    float2 r; asm("mov.b64 {%0, %1}, %2;" : "=f"(r.x), "=f"(r.y) : "l"(v)); return r;
}
__device__ __forceinline__ void fma2(ull &d, ull a, ull b) {
    asm("fma.rn.f32x2 %0, %1, %2, %0;" : "+l"(d) : "l"(a), "l"(b));
}

// ---------------- K0a: twiddle tables (m 0..181) + zero stats ---------------
__global__ void k0_tables() {
    int tid = blockIdx.x * blockDim.x + threadIdx.x;
    int stride = gridDim.x * blockDim.x;
    const int NT = NPAD * MP2;
    for (int i = tid; i < NT; i += stride) {
        int n = i / MP2, mp = i - (i / MP2) * MP2;
        float c0 = 0.f, s0 = 0.f, c1 = 0.f, s1 = 0.f;
        if (n <= 360) {
            int m0 = 2 * mp, m1 = m0 + 1;
            if (m0 <= 181) {
                float s, c;
                sincospif((float)((n * m0) % NLON) / 360.f, &s, &c);
                c0 = c; s0 = -s;
            }
            if (m1 <= 181) {
                float s, c;
                sincospif((float)((n * m1) % NLON) / 360.f, &s, &c);
                c1 = c; s1 = -s;
            }
        }
        g_Bc[i] = make_float2(c0, c1);
        g_Bs[i] = make_float2(s0, s1);
    }
    for (int i = tid; i < KDEG * NBC * 4; i += stride) g_stats[i] = 0.f;
}

// ---------------- K0b: fold rows into sum/diff with quadrature scale --------
__global__ void k0b_sd(const float* __restrict__ pred,
                       const float* __restrict__ targ,
                       const float* __restrict__ w) {
    const int NQ = NPAD / 4;  // 96 float4 per row
    int id = blockIdx.x * blockDim.x + threadIdx.x;
    if (id >= R_PAD * NQ) return;
    int r = id / NQ;
    int n = (id - r * NQ) * 4;
    float4 sv = make_float4(0.f, 0.f, 0.f, 0.f);
    float4 dv = make_float4(0.f, 0.f, 0.f, 0.f);
    if (r < R_TOT) {
        int tensor = r / HALF_R;
        int rem = r - tensor * HALF_R;
        int j = rem % NLAT;
        float wsc = w[j] * (2.f * PI_F / (float)NLON);
        const float* a = (tensor ? targ : pred) + (size_t)rem * NLON;
        float4 af = *(const float4*)(a + n);
        float fa[4] = {af.x, af.y, af.z, af.w};
        float so[4], dd[4];
#pragma unroll
        for (int e = 0; e < 4; e++) {
            int nn = n + e;
            float av = (nn <= 360) ? fa[e] : 0.f;
            float mv = (nn >= 1 && nn <= 359) ? a[NLON - nn] : 0.f;
            so[e] = (av + mv) * wsc;
            dd[e] = (av - mv) * wsc;
        }
        sv = make_float4(so[0], so[1], so[2], so[3]);
        dv = make_float4(dd[0], dd[1], dd[2], dd[3]);
    }
    *(float4*)&g_S[(size_t)r * NPAD + n] = sv;
    *(float4*)&g_D[(size_t)r * NPAD + n] = dv;
}

// ---------------- K1: folded DFT with m <-> 360-m mirror fold ---------------
__global__ __launch_bounds__(128, 4) void k1_dft() {
    __shared__ float2 Ss[32][16];     // [row][q] = {s[2q], s[2q+1]}
    __shared__ float2 Ds[32][16];
    __shared__ float2 Cs[32][32];     // [n_local][mp]
    __shared__ float2 Sn[32][32];

    const int t    = threadIdx.x;
    const int mp0  = blockIdx.x * 32;
    const int row0 = blockIdx.y * 32;
    const int tcol = t & 15;
    const int trow = t >> 4;
    const int tc2  = tcol * 2;

    ull aCe[4][2], aCo[4][2], aSe[4][2], aSo[4][2];
    const ull z = pk2(0.f, 0.f);
#pragma unroll
    for (int i = 0; i < 4; i++)
#pragma unroll
        for (int p = 0; p < 2; p++) {
            aCe[i][p] = z; aCo[i][p] = z; aSe[i][p] = z; aSo[i][p] = z;
        }

    for (int kt = 0; kt < 12; kt++) {
        const int k0 = kt * 32;
#pragma unroll
        for (int q = 0; q < 2; q++) {
            int f = t + q * 128;
            int row = f >> 3, c4 = f & 7;
            size_t gi = (size_t)(row0 + row) * NPAD + k0 + c4 * 4;
            float4 v = *(const float4*)&g_S[gi];
            Ss[row][c4 * 2]     = make_float2(v.x, v.y);
            Ss[row][c4 * 2 + 1] = make_float2(v.z, v.w);
            float4 u = *(const float4*)&g_D[gi];
            Ds[row][c4 * 2]     = make_float2(u.x, u.y);
            Ds[row][c4 * 2 + 1] = make_float2(u.z, u.w);
        }
#pragma unroll
        for (int q = 0; q < 4; q++) {
            int e = t + q * 128;
            int nl = e >> 4, f4 = e & 15;
            size_t gi = (size_t)(k0 + nl) * MP2 + mp0;
            ((float4*)&Cs[nl][0])[f4] = ((const float4*)&g_Bc[gi])[f4];
            ((float4*)&Sn[nl][0])[f4] = ((const float4*)&g_Bs[gi])[f4];
        }
        __syncthreads();
#pragma unroll 4
        for (int q = 0; q < 16; q++) {
            ulonglong2 ce = *(const ulonglong2*)&Cs[2 * q][tc2];
            ulonglong2 co = *(const ulonglong2*)&Cs[2 * q + 1][tc2];
            ulonglong2 se = *(const ulonglong2*)&Sn[2 * q][tc2];
            ulonglong2 so = *(const ulonglong2*)&Sn[2 * q + 1][tc2];
#pragma unroll
            for (int i = 0; i < 4; i++) {
                float2 sv = Ss[trow * 4 + i][q];
                float2 dv = Ds[trow * 4 + i][q];
                ull sae = pk2(sv.x, sv.x), sao = pk2(sv.y, sv.y);
                ull dae = pk2(dv.x, dv.x), dao = pk2(dv.y, dv.y);
                fma2(aCe[i][0], sae, ce.x); fma2(aCe[i][1], sae, ce.y);
                fma2(aCo[i][0], sao, co.x); fma2(aCo[i][1], sao, co.y);
                fma2(aSe[i][0], dae, se.x); fma2(aSe[i][1], dae, se.y);
                fma2(aSo[i][0], dao, so.x); fma2(aSo[i][1], dao, so.y);
            }
        }
        __syncthreads();
    }

#pragma unroll
    for (int i = 0; i < 4; i++) {
        int gr = row0 + trow * 4 + i;
        if (gr >= R_TOT) continue;
        int tensor = gr / HALF_R;
        int rem = gr - tensor * HALF_R;
        int bc = rem / NLAT;
        int j  = rem - bc * NLAT;
        int c  = tensor * 16 + bc;
        float2* Fc = &g_F[(size_t)c * NLAT + j];
#pragma unroll
        for (int p = 0; p < 2; p++) {
            int g  = mp0 + tc2 + p;
            int m0 = 2 * g, m1 = m0 + 1;
            float2 ce = upk2(aCe[i][p]), co = upk2(aCo[i][p]);
            float2 se = upk2(aSe[i][p]), so = upk2(aSo[i][p]);
            if (m0 <= 180)
                Fc[(size_t)m0 * (NCH * NLAT)] = make_float2(ce.x + co.x, se.x + so.x);
            if (m1 <= 180)
                Fc[(size_t)m1 * (NCH * NLAT)] = make_float2(ce.y + co.y, se.y + so.y);
            if (m0 <= 179)
                Fc[(size_t)(360 - m0) * (NCH * NLAT)] =
                    make_float2(ce.x - co.x, -se.x + so.x);
            if (m1 <= 179)
                Fc[(size_t)(360 - m1) * (NCH * NLAT)] =
                    make_float2(ce.y - co.y, -se.y + so.y);
        }
    }
}

// ---------------- K2: Legendre contraction, parity fold, reg double-buffer --
#define TJ 16
#define NTILE 12
__global__ __launch_bounds__(128, 4) void k2_leg(const float* __restrict__ leg) {
    const int m  = blockIdx.y;                 // 0..359
    const int l0 = m + blockIdx.x * 128;
    if (l0 >= KDEG) return;

    __shared__ float2 Fse[TJ][34];             // even-fold F, [j][ch]
    __shared__ float2 Fso[TJ][34];             // odd-fold F
    __shared__ float2 Ls2[128][17];            // leg duplicated {v,v}

    const int t   = threadIdx.x;
    const int cg  = t & 7;
    const int lg  = t >> 3;
    const int ch0 = cg * 4;
    const int lb  = lg * 8;

    const int jl_s = t & 15;                   // staging j index
    const int hi4  = t >> 4;                   // 0..7

    ull acc[8][4];
    const ull z = pk2(0.f, 0.f);
#pragma unroll
    for (int i = 0; i < 8; i++)
#pragma unroll
        for (int k = 0; k < 4; k++) acc[i][k] = z;

    const float2* Fm = &g_F[(size_t)m * NCH * NLAT];

    float2 pf[4], pg[4];                       // F prefetch (4 channels)
    float  pl[16];                             // leg prefetch (16 l rows)

    // ---- prologue: prefetch tile 0 into registers ----
    {
        const int j = jl_s;                    // j0 = 0
#pragma unroll
        for (int q = 0; q < 4; q++) {
            int c = hi4 + 8 * q;
            pf[q] = Fm[(size_t)c * NLAT + j];
            pg[q] = Fm[(size_t)c * NLAT + 360 - j];
        }
#pragma unroll
        for (int q = 0; q < 16; q++) {
            int l = l0 + hi4 + 8 * q;
            pl[q] = (l <= 360) ? leg[((size_t)l * NLAT + m) * NLAT + j] : 0.f;
        }
    }

    for (int tile = 0; tile < NTILE; tile++) {
        // ---- commit prefetched tile to smem ----
#pragma unroll
        for (int q = 0; q < 4; q++) {
            int c = hi4 + 8 * q;
            Fse[jl_s][c] = make_float2(pf[q].x + pg[q].x, pf[q].y + pg[q].y);
            Fso[jl_s][c] = make_float2(pf[q].x - pg[q].x, pf[q].y - pg[q].y);
        }
#pragma unroll
        for (int q = 0; q < 16; q++)
            Ls2[hi4 + 8 * q][jl_s] = make_float2(pl[q], pl[q]);
        __syncthreads();

        // ---- prefetch next tile (overlaps with compute below) ----
        if (tile + 1 < NTILE) {
            const int j = (tile + 1) * TJ + jl_s;
#pragma unroll
            for (int q = 0; q < 4; q++) {
                int c = hi4 + 8 * q;
                pf[q] = (j <= 180) ? Fm[(size_t)c * NLAT + j]
                                   : make_float2(0.f, 0.f);
                pg[q] = (j <  180) ? Fm[(size_t)c * NLAT + 360 - j]
                                   : make_float2(0.f, 0.f);
            }
#pragma unroll
            for (int q = 0; q < 16; q++) {
                int l = l0 + hi4 + 8 * q;
                pl[q] = (j <= 180 && l <= 360)
                            ? leg[((size_t)l * NLAT + m) * NLAT + j] : 0.f;
            }
        }

        // ---- compute current tile ----
#pragma unroll 4
        for (int jl = 0; jl < TJ; jl++) {
            ulonglong2 fe01 = *(const ulonglong2*)&Fse[jl][ch0];
            ulonglong2 fe23 = *(const ulonglong2*)&Fse[jl][ch0 + 2];
            ulonglong2 fo01 = *(const ulonglong2*)&Fso[jl][ch0];
            ulonglong2 fo23 = *(const ulonglong2*)&Fso[jl][ch0 + 2];
#pragma unroll
            for (int i = 0; i < 8; i++) {
                ull l2 = *(const ull*)&Ls2[lb + i][jl];
                if (i & 1) {
                    fma2(acc[i][0], l2, fo01.x); fma2(acc[i][1], l2, fo01.y);
                    fma2(acc[i][2], l2, fo23.x); fma2(acc[i][3], l2, fo23.y);
                } else {
                    fma2(acc[i][0], l2, fe01.x); fma2(acc[i][1], l2, fe01.y);
                    fma2(acc[i][2], l2, fe23.x); fma2(acc[i][3], l2, fe23.y);
                }
            }
        }
        __syncthreads();
    }

    // epilogue: pair P (cg<4) with T (cg+4) via shfl, atomically accumulate
    const float wm = (m == 0) ? 1.f : 2.f;
#pragma unroll
    for (int i = 0; i < 8; i++) {
        int l = l0 + lb + i;
#pragma unroll
        for (int k = 0; k < 4; k++) {
            float2 cv = upk2(acc[i][k]);
            float ox = __shfl_xor_sync(0xffffffffu, cv.x, 4);
            float oy = __shfl_xor_sync(0xffffffffu, cv.y, 4);
            if (cg < 4 && l < KDEG) {
                float pp  = cv.x * cv.x + cv.y * cv.y;
                float tp  = ox * ox + oy * oy;
                float crr = cv.x * ox + cv.y * oy;
                float cii = cv.x * oy - cv.y * ox;
                float* s = &g_stats[(l * NBC + ch0 + k) * 4];
                atomicAdd(s + 0, wm * pp);
                atomicAdd(s + 1, wm * tp);
                atomicAdd(s + 2, wm * crr);
                atomicAdd(s + 3, wm * cii);
            }
        }
    }
}

// ---------------- K3: final loss --------------------------------------------
__global__ void k3_final(const float* __restrict__ weights, float* __restrict__ out) {
    __shared__ float red[32];
    const int t = threadIdx.x;                 // 1024 threads
    float part = 0.f;
    for (int i = t; i < KDEG * NBC; i += 1024) {
        float4 s = *(const float4*)&g_stats[i * 4];
        int bc = i & 15;
        float pp = s.x + EPSV;
        float tp = s.y + EPSV;
        float mag = sqrtf(s.z * s.z + s.w * s.w);
        float den = sqrtf(pp * tp + EPSV) + EPSV;
        float coh = fminf(mag / den, 1.f);
        float sp = sqrtf(pp), st = sqrtf(tp);
        float amp = (sp - st) * (sp - st);
        float dec = 2.f * fmaxf(pp, tp) * (1.f - coh);
        part += weights[bc & 7] * (amp + dec);
    }
#pragma unroll
    for (int o = 16; o > 0; o >>= 1) part += __shfl_down_sync(0xffffffffu, part, o);
    if ((t & 31) == 0) red[t >> 5] = part;
    __syncthreads();
    if (t < 32) {
        float v = red[t];
#pragma unroll
        for (int o = 16; o > 0; o >>= 1) v += __shfl_down_sync(0xffffffffu, v, o);
        if (t == 0) {
            float loss = v / (float)(KDEG * NBC);
            if (isnan(loss)) loss = 1e6f;
            out[0] = loss;
        }
    }
}

// ---------------- launcher ---------------------------------------------------
extern "C" void kernel_launch(void* const* d_in, const int* in_sizes, int n_in,
                              void* d_out, int out_size) {
    const float* pred    = (const float*)d_in[0];
    const float* targ    = (const float*)d_in[1];
    const float* weights = (const float*)d_in[2];
    const float* leg     = (const float*)d_in[3];
    const float* w       = (const float*)d_in[4];

    k0_tables<<<144, 256>>>();

    int tot0 = R_PAD * (NPAD / 4);
    k0b_sd<<<(tot0 + 255) / 256, 256>>>(pred, targ, w);

    dim3 g1(3, 362);            // 32 mp-tiles x 32-row tiles
    k1_dft<<<g1, 128>>>();

    dim3 g2(3, KDEG);           // 128-l tiles x m
    k2_leg<<<g2, 128>>>(leg);

    k3_final<<<1, 1024>>>(weights, (float*)d_out);
}